// round 1
// baseline (speedup 1.0000x reference)
#include <cuda_runtime.h>
#include <math.h>

#define BB 128
#define SS 512
#define NN 32
#define DD 512
#define HH 2
#define MM (BB*NN)   // 4096 rows

// ---------------- scratch (device globals; no allocation) ----------------
__device__ float g_gt_buf[BB*NN*NN];
__device__ float g_lt_buf[BB*NN*NN];
__device__ float buf_nodeA[MM*DD];
__device__ float buf_nodeB[MM*DD];
__device__ float buf_t1[MM*DD];
__device__ float buf_t2[MM*DD];
__device__ float buf_ni1[MM*DD];
__device__ float buf_ni2[MM*DD];
__device__ float buf_ninfo[MM*DD];
__device__ float buf_Wg1[DD*DD];
__device__ float buf_Wg2[DD*DD];

// ---------------- graph construction ----------------
// g_gt = rownorm(pair*greater + I), g_lt = rownorm(pair*(~greater) + I)
__global__ void build_graphs(const int* __restrict__ order,
                             float* __restrict__ g_gt, float* __restrict__ g_lt) {
    int b = blockIdx.x;
    __shared__ int ord[NN];
    int tid = threadIdx.x;              // 1024 threads = NN*NN
    if (tid < NN) ord[tid] = order[b*NN + tid];
    __syncthreads();
    int n = tid >> 5, m = tid & 31;
    int on = ord[n], om = ord[m];
    float pair = (on > 0 && om > 0 && n != m) ? 1.f : 0.f;
    float eye  = (n == m) ? 1.f : 0.f;
    float vg = pair * ((on > om) ? 1.f : 0.f) + eye;
    float vl = pair * ((on > om) ? 0.f : 1.f) + eye;
    float sg = vg, sl = vl;
    #pragma unroll
    for (int off = 16; off; off >>= 1) {
        sg += __shfl_xor_sync(0xffffffffu, sg, off);
        sl += __shfl_xor_sync(0xffffffffu, sl, off);
    }
    g_gt[b*NN*NN + tid] = vg / sg;
    g_lt[b*NN*NN + tid] = vl / sl;
}

// ---------------- batched graph aggregation: y[b,n,:] = sum_m g[b,n,m] x[b,m,:] ----
__global__ void graph_agg(const float* __restrict__ g, const float* __restrict__ x,
                          float* __restrict__ y) {
    int b = blockIdx.x;
    int d = threadIdx.x;                // 512 threads
    __shared__ float gs[NN*NN];
    for (int i = threadIdx.x; i < NN*NN; i += blockDim.x) gs[i] = g[b*NN*NN + i];
    __syncthreads();
    const float* xb = x + (size_t)b*NN*DD + d;
    float xv[NN];
    #pragma unroll
    for (int m = 0; m < NN; m++) xv[m] = xb[(size_t)m*DD];
    float* yb = y + (size_t)b*NN*DD + d;
    #pragma unroll
    for (int n = 0; n < NN; n++) {
        float acc = 0.f;
        #pragma unroll
        for (int m = 0; m < NN; m++) acc = fmaf(gs[n*NN+m], xv[m], acc);
        yb[(size_t)n*DD] = acc;
    }
}

// ---------------- combined gate weights: Wg1 = w0+w2+w3, Wg2 = w1+w2-w3 ----------
__global__ void prep_gate_w(const float* __restrict__ wg,
                            float* __restrict__ W1, float* __restrict__ W2) {
    int idx = blockIdx.x*blockDim.x + threadIdx.x;   // DD*DD
    if (idx >= DD*DD) return;
    int k = idx / DD, e = idx % DD;
    float w0 = wg[(size_t)k*DD + e];
    float w1 = wg[(size_t)(DD+k)*DD + e];
    float w2 = wg[(size_t)(2*DD+k)*DD + e];
    float w3 = wg[(size_t)(3*DD+k)*DD + e];
    W1[idx] = w0 + w2 + w3;
    W2[idx] = w1 + w2 - w3;
}

// ---------------- SGEMM: out = epi(A1@W1 (+ A2@W2) + bias) ----------------
// M=4096, N=512, K=512 per pair. 128x128 tile, BK=8, 256 threads, 8x8/thread.
// EPI 1: relu.  EPI 2: gate = sigmoid(v); out = gate*e1 + (1-gate)*e2.
template<int EPI>
__global__ void __launch_bounds__(256)
gemm_dd(const float* __restrict__ A1, const float* __restrict__ W1,
        const float* __restrict__ A2, const float* __restrict__ W2,
        const float* __restrict__ bias,
        const float* e1, const float* e2,
        float* __restrict__ out)
{
    const int bm = blockIdx.y * 128;
    const int bn = blockIdx.x * 128;
    __shared__ float As[8][128];
    __shared__ float Bs[8][128];
    const int tid = threadIdx.x;
    const int a_row = tid >> 1;
    const int a_col = (tid & 1) << 2;
    const int b_row = tid >> 5;
    const int b_col = (tid & 31) << 2;
    const int tx = tid & 15;
    const int ty = tid >> 4;
    const int nK = A2 ? 1024 : 512;

    float acc[8][8];
    #pragma unroll
    for (int i = 0; i < 8; i++)
        #pragma unroll
        for (int j = 0; j < 8; j++) acc[i][j] = 0.f;

    // prefetch tile 0
    float4 av = *(const float4*)(A1 + (size_t)(bm + a_row)*512 + a_col);
    float4 bv = *(const float4*)(W1 + (size_t)b_row*512 + bn + b_col);

    for (int k0 = 0; k0 < nK; k0 += 8) {
        __syncthreads();
        As[a_col+0][a_row] = av.x;
        As[a_col+1][a_row] = av.y;
        As[a_col+2][a_row] = av.z;
        As[a_col+3][a_row] = av.w;
        *(float4*)&Bs[b_row][b_col] = bv;
        __syncthreads();
        int k1 = k0 + 8;
        if (k1 < nK) {  // prefetch next tile (overlaps compute below)
            const float* A = (k1 < 512) ? A1 : A2;
            const float* W = (k1 < 512) ? W1 : W2;
            int kk = k1 & 511;
            av = *(const float4*)(A + (size_t)(bm + a_row)*512 + kk + a_col);
            bv = *(const float4*)(W + (size_t)(kk + b_row)*512 + bn + b_col);
        }
        #pragma unroll
        for (int k = 0; k < 8; k++) {
            float4 a0 = *(const float4*)&As[k][ty*8];
            float4 a1 = *(const float4*)&As[k][ty*8+4];
            float4 b0 = *(const float4*)&Bs[k][tx*8];
            float4 b1 = *(const float4*)&Bs[k][tx*8+4];
            float ra[8] = {a0.x,a0.y,a0.z,a0.w,a1.x,a1.y,a1.z,a1.w};
            float rb[8] = {b0.x,b0.y,b0.z,b0.w,b1.x,b1.y,b1.z,b1.w};
            #pragma unroll
            for (int i = 0; i < 8; i++)
                #pragma unroll
                for (int j = 0; j < 8; j++)
                    acc[i][j] = fmaf(ra[i], rb[j], acc[i][j]);
        }
    }

    float bb[8];
    #pragma unroll
    for (int j = 0; j < 8; j++) bb[j] = bias[bn + tx*8 + j];

    #pragma unroll
    for (int i = 0; i < 8; i++) {
        int row = bm + ty*8 + i;
        float* orow = out + (size_t)row*512 + bn + tx*8;
        float res[8];
        #pragma unroll
        for (int j = 0; j < 8; j++) {
            float v = acc[i][j] + bb[j];
            if (EPI == 1) {
                v = fmaxf(v, 0.f);
            } else {
                float gte = 1.f / (1.f + expf(-v));
                const float* e1r = e1 + (size_t)row*512 + bn + tx*8;
                const float* e2r = e2 + (size_t)row*512 + bn + tx*8;
                v = gte * e1r[j] + (1.f - gte) * e2r[j];
            }
            res[j] = v;
        }
        *(float4*)orow     = make_float4(res[0],res[1],res[2],res[3]);
        *(float4*)(orow+4) = make_float4(res[4],res[5],res[6],res[7]);
    }
}

// ---------------- output assembly ----------------
__global__ void copy_f4(const float4* __restrict__ src, float4* __restrict__ dst, int n4) {
    int i = blockIdx.x*blockDim.x + threadIdx.x;
    int stride = gridDim.x*blockDim.x;
    for (; i < n4; i += stride) dst[i] = src[i];
}

__global__ void add_f4(const float4* __restrict__ a, const float4* __restrict__ b,
                       float4* __restrict__ dst, int n4) {
    int i = blockIdx.x*blockDim.x + threadIdx.x;
    int stride = gridDim.x*blockDim.x;
    for (; i < n4; i += stride) {
        float4 x = a[i], y = b[i];
        dst[i] = make_float4(x.x+y.x, x.y+y.y, x.z+y.z, x.w+y.w);
    }
}

// gnn[p, b, :] += node[b, n, :]  for valid positions (distinct per row)
__global__ void scatter_node(const int* __restrict__ pos, const float* __restrict__ node,
                             float* __restrict__ gnn) {
    int bn = blockIdx.x;                 // b*NN + n
    int b = bn >> 5;
    int p = pos[bn];
    if (p < 0) return;
    const float4* src = (const float4*)(node + (size_t)bn * DD);
    float4* dst = (float4*)(gnn + ((size_t)p * BB + b) * DD);
    int t = threadIdx.x;                 // 128 threads, DD/4 = 128 float4
    float4 v = src[t];
    float4 d = dst[t];
    d.x += v.x; d.y += v.y; d.z += v.z; d.w += v.w;
    dst[t] = d;
}

__global__ void colmax(const float* __restrict__ gnn, float* __restrict__ po) {
    int idx = blockIdx.x*blockDim.x + threadIdx.x;   // over BB*DD
    if (idx >= BB*DD) return;
    float m = -__int_as_float(0x7f800000) * 0.f - 3.402823466e38f;
    m = -3.402823466e38f;
    for (int s = 0; s < SS; s++)
        m = fmaxf(m, gnn[(size_t)s*BB*DD + idx]);
    po[idx] = m;
}

// ---------------- host launch ----------------
extern "C" void kernel_launch(void* const* d_in, const int* in_sizes, int n_in,
                              void* d_out, int out_size) {
    const float* enc    = (const float*)d_in[0];   // [S,B,D]
    const float* numenc = (const float*)d_in[1];   // [B,N,D]
    const int*   pos    = (const int*)d_in[2];     // [B,N]
    const int*   order  = (const int*)d_in[3];     // [B,N]
    const float* w_n1a  = (const float*)d_in[4];
    const float* b_n1a  = (const float*)d_in[5];
    const float* w_n1b  = (const float*)d_in[6];
    const float* b_n1b  = (const float*)d_in[7];
    const float* w_n2a  = (const float*)d_in[8];
    const float* b_n2a  = (const float*)d_in[9];
    const float* w_n2b  = (const float*)d_in[10];
    const float* b_n2b  = (const float*)d_in[11];
    const float* w_g    = (const float*)d_in[12];  // [H,4D,D]
    const float* b_g    = (const float*)d_in[13];
    const float* w_o    = (const float*)d_in[14];  // [H,2D,D]
    const float* b_o    = (const float*)d_in[15];

    float* out     = (float*)d_out;
    float* out_gnn = out;                                    // [S,B,D]
    float* out_ne  = out + (size_t)SS*BB*DD;                 // [B,N,D]
    float* out_po  = out_ne + (size_t)BB*NN*DD;              // [B,D]

    float *g_gt, *g_lt, *nodeA, *nodeB, *t1, *t2, *ni1, *ni2, *ninfo, *Wg1, *Wg2;
    cudaGetSymbolAddress((void**)&g_gt,  g_gt_buf);
    cudaGetSymbolAddress((void**)&g_lt,  g_lt_buf);
    cudaGetSymbolAddress((void**)&nodeA, buf_nodeA);
    cudaGetSymbolAddress((void**)&nodeB, buf_nodeB);
    cudaGetSymbolAddress((void**)&t1,    buf_t1);
    cudaGetSymbolAddress((void**)&t2,    buf_t2);
    cudaGetSymbolAddress((void**)&ni1,   buf_ni1);
    cudaGetSymbolAddress((void**)&ni2,   buf_ni2);
    cudaGetSymbolAddress((void**)&ninfo, buf_ninfo);
    cudaGetSymbolAddress((void**)&Wg1,   buf_Wg1);
    cudaGetSymbolAddress((void**)&Wg2,   buf_Wg2);

    dim3 gblk(4, 32);   // N tiles (512/128), M tiles (4096/128)

    build_graphs<<<BB, NN*NN>>>(order, g_gt, g_lt);
    copy_f4<<<2048, 256>>>((const float4*)numenc, (float4*)nodeA, MM*DD/4);

    float* node  = nodeA;
    float* nodeN = nodeB;
    for (int h = 0; h < HH; h++) {
        prep_gate_w<<<(DD*DD + 255)/256, 256>>>(w_g + (size_t)h*4*DD*DD, Wg1, Wg2);

        graph_agg<<<BB, DD>>>(g_gt, node, t1);
        gemm_dd<1><<<gblk, 256>>>(t1, w_n1a + (size_t)h*DD*DD, nullptr, nullptr,
                                  b_n1a + h*DD, nullptr, nullptr, t2);
        graph_agg<<<BB, DD>>>(g_gt, t2, t1);
        gemm_dd<1><<<gblk, 256>>>(t1, w_n1b + (size_t)h*DD*DD, nullptr, nullptr,
                                  b_n1b + h*DD, nullptr, nullptr, ni1);

        graph_agg<<<BB, DD>>>(g_lt, node, t1);
        gemm_dd<1><<<gblk, 256>>>(t1, w_n2a + (size_t)h*DD*DD, nullptr, nullptr,
                                  b_n2a + h*DD, nullptr, nullptr, t2);
        graph_agg<<<BB, DD>>>(g_lt, t2, t1);
        gemm_dd<1><<<gblk, 256>>>(t1, w_n2b + (size_t)h*DD*DD, nullptr, nullptr,
                                  b_n2b + h*DD, nullptr, nullptr, ni2);

        // node_info = sigmoid(ni1@Wg1 + ni2@Wg2 + b_g)*ni1 + (1-.)*ni2
        gemm_dd<2><<<gblk, 256>>>(ni1, Wg1, ni2, Wg2, b_g + h*DD, ni1, ni2, ninfo);

        // node = relu(node@w_o[:D] + node_info@w_o[D:] + b_o)
        gemm_dd<1><<<gblk, 256>>>(node, w_o + (size_t)h*2*DD*DD,
                                  ninfo, w_o + (size_t)h*2*DD*DD + (size_t)DD*DD,
                                  b_o + h*DD, nullptr, nullptr, nodeN);
        float* tmp = node; node = nodeN; nodeN = tmp;
    }

    copy_f4<<<4096, 256>>>((const float4*)enc, (float4*)out_gnn, SS*BB*DD/4);
    scatter_node<<<BB*NN, 128>>>(pos, node, out_gnn);
    add_f4<<<2048, 256>>>((const float4*)numenc, (const float4*)node,
                          (float4*)out_ne, BB*NN*DD/4);
    colmax<<<BB*DD/256, 256>>>(out_gnn, out_po);
}

// round 3
// speedup vs baseline: 2.9449x; 2.9449x over previous
#include <cuda_runtime.h>
#include <math.h>
#include <stdint.h>

#define BB 128
#define SS 512
#define NN 32
#define DD 512
#define HH 2
#define MM (BB*NN)   // 4096 rows

#define KCH 32                 // K elements per pipeline chunk
#define APITCH 36              // smem row pitch in floats (conflict-free frags)
#define STG_FLTS (128*APITCH)  // 4608 floats per matrix per stage
#define SMEM_DYN (2*2*STG_FLTS*4)   // 2 stages x (A+B) = 73728 bytes

// ---------------- scratch (device globals; no allocation) ----------------
__device__ float g_gt_buf[BB*NN*NN];
__device__ float g_lt_buf[BB*NN*NN];
__device__ int   invmap_buf[BB*SS];
__device__ float buf_nodeA[MM*DD];
__device__ float buf_nodeB[MM*DD];
__device__ float buf_t1[MM*DD];
__device__ float buf_t2[MM*DD];
__device__ float buf_t3[MM*DD];
__device__ float buf_t4[MM*DD];
__device__ float buf_ni1[MM*DD];
__device__ float buf_ni2[MM*DD];
__device__ float buf_ninfo[MM*DD];
__device__ float buf_WT[16*DD*DD];   // 16 transposed (tf32-rounded) weights [N,K]

// ---------------- helpers ----------------
__device__ __forceinline__ uint32_t smem_u32(const void* p) {
    return (uint32_t)__cvta_generic_to_shared(p);
}
__device__ __forceinline__ float to_tf32(float x) {
    uint32_t r; asm("cvt.rna.tf32.f32 %0, %1;" : "=r"(r) : "f"(x));
    return __uint_as_float(r);
}
__device__ __forceinline__ void cp_async16(uint32_t dst, const void* src) {
    asm volatile("cp.async.cg.shared.global [%0], [%1], 16;" :: "r"(dst), "l"(src));
}
__device__ __forceinline__ void mma_tf32(float* c, const uint32_t* a,
                                         uint32_t b0, uint32_t b1) {
    asm volatile("mma.sync.aligned.m16n8k8.row.col.f32.tf32.tf32.f32 "
                 "{%0,%1,%2,%3}, {%4,%5,%6,%7}, {%8,%9}, {%0,%1,%2,%3};"
                 : "+f"(c[0]), "+f"(c[1]), "+f"(c[2]), "+f"(c[3])
                 : "r"(a[0]), "r"(a[1]), "r"(a[2]), "r"(a[3]), "r"(b0), "r"(b1));
}

// ---------------- graph construction ----------------
__global__ void build_graphs(const int* __restrict__ order,
                             float* __restrict__ g_gt, float* __restrict__ g_lt) {
    int b = blockIdx.x;
    __shared__ int ord[NN];
    int tid = threadIdx.x;              // 1024 threads = NN*NN
    if (tid < NN) ord[tid] = order[b*NN + tid];
    __syncthreads();
    int n = tid >> 5, m = tid & 31;
    int on = ord[n], om = ord[m];
    float pair = (on > 0 && om > 0 && n != m) ? 1.f : 0.f;
    float eye  = (n == m) ? 1.f : 0.f;
    float vg = pair * ((on > om) ? 1.f : 0.f) + eye;
    float vl = pair * ((on > om) ? 0.f : 1.f) + eye;
    float sg = vg, sl = vl;
    #pragma unroll
    for (int off = 16; off; off >>= 1) {
        sg += __shfl_xor_sync(0xffffffffu, sg, off);
        sl += __shfl_xor_sync(0xffffffffu, sl, off);
    }
    g_gt[b*NN*NN + tid] = vg / sg;
    g_lt[b*NN*NN + tid] = vl / sl;
}

__global__ void build_invmap(const int* __restrict__ pos, int* __restrict__ invmap) {
    int b = blockIdx.x;
    invmap[b*SS + threadIdx.x] = -1;    // 512 threads
    __syncthreads();
    if (threadIdx.x < NN) {
        int p = pos[b*NN + threadIdx.x];
        if (p >= 0) invmap[b*SS + p] = b*NN + threadIdx.x;
    }
}

// ---------------- dual graph aggregation (z=0: gt/x0->y0, z=1: lt/x1->y1) ------
__global__ void graph_agg2(const float* __restrict__ g_gt, const float* __restrict__ g_lt,
                           const float* __restrict__ x0, const float* __restrict__ x1,
                           float* __restrict__ y0, float* __restrict__ y1) {
    int b = blockIdx.x;
    const float* g = blockIdx.z ? g_lt : g_gt;
    const float* x = blockIdx.z ? x1 : x0;
    float* y       = blockIdx.z ? y1 : y0;
    int d = blockIdx.y * 128 + threadIdx.x;    // 128 threads
    __shared__ float gs[NN*NN];
    for (int i = threadIdx.x; i < NN*NN; i += 128) gs[i] = g[b*NN*NN + i];
    __syncthreads();
    const float* xb = x + (size_t)b*NN*DD + d;
    float xv[NN];
    #pragma unroll
    for (int m = 0; m < NN; m++) xv[m] = xb[(size_t)m*DD];
    float* yb = y + (size_t)b*NN*DD + d;
    #pragma unroll
    for (int n = 0; n < NN; n++) {
        float acc = 0.f;
        #pragma unroll
        for (int m = 0; m < NN; m++) acc = fmaf(gs[n*NN+m], xv[m], acc);
        yb[(size_t)n*DD] = acc;
    }
}

// ---------------- weight transposes ([K,N] -> [N,K], tf32-rounded) ----------
__global__ void transpose_w(const float* __restrict__ src, float* __restrict__ dst) {
    __shared__ float t[32][33];
    int k0 = blockIdx.x*32, n0 = blockIdx.y*32;
    #pragma unroll
    for (int i = 0; i < 4; i++)
        t[threadIdx.y + i*8][threadIdx.x] =
            src[(size_t)(k0 + threadIdx.y + i*8)*DD + n0 + threadIdx.x];
    __syncthreads();
    #pragma unroll
    for (int i = 0; i < 4; i++)
        dst[(size_t)(n0 + threadIdx.y + i*8)*DD + k0 + threadIdx.x] =
            to_tf32(t[threadIdx.x][threadIdx.y + i*8]);
}

__global__ void transpose_gate(const float* __restrict__ wg,
                               float* __restrict__ d1, float* __restrict__ d2) {
    __shared__ float t1s[32][33], t2s[32][33];
    int k0 = blockIdx.x*32, n0 = blockIdx.y*32;
    #pragma unroll
    for (int i = 0; i < 4; i++) {
        int k = k0 + threadIdx.y + i*8, n = n0 + threadIdx.x;
        float w0 = wg[(size_t)k*DD + n];
        float w1 = wg[(size_t)(DD + k)*DD + n];
        float w2 = wg[(size_t)(2*DD + k)*DD + n];
        float w3 = wg[(size_t)(3*DD + k)*DD + n];
        t1s[threadIdx.y + i*8][threadIdx.x] = w0 + w2 + w3;
        t2s[threadIdx.y + i*8][threadIdx.x] = w1 + w2 - w3;
    }
    __syncthreads();
    #pragma unroll
    for (int i = 0; i < 4; i++) {
        size_t o = (size_t)(n0 + threadIdx.y + i*8)*DD + k0 + threadIdx.x;
        d1[o] = to_tf32(t1s[threadIdx.x][threadIdx.y + i*8]);
        d2[o] = to_tf32(t2s[threadIdx.x][threadIdx.y + i*8]);
    }
}

// ---------------- TF32 mma.sync GEMM ----------------
// out_z = epi(A1_z @ W1_z^T (+ A2_z @ W2_z^T) + bias_z)
// A: [4096,512] fp32 row-major; W: [N,K] fp32 (tf32-rounded) row-major.
// EPI 1: relu.  EPI 2: g = sigmoid(v); out = g*e1 + (1-g)*e2.
struct GemmPair {
    const float *A1[2], *W1[2], *A2[2], *W2[2], *bias[2];
    const float *e1, *e2;
    float *out[2];
    int nK;
};

__device__ __forceinline__ void load_chunk(float* smbase, const float* Asrc,
                                           const float* Wsrc, int bm, int bn,
                                           int kk, int tid) {
    float* Asm = smbase;
    float* Bsm = smbase + STG_FLTS;
    #pragma unroll
    for (int j = 0; j < 4; j++) {
        int f = tid + 256*j; int row = f >> 3, c4 = f & 7;
        cp_async16(smem_u32(Asm + row*APITCH + c4*4),
                   Asrc + (size_t)(bm + row)*512 + kk + c4*4);
    }
    #pragma unroll
    for (int j = 0; j < 4; j++) {
        int f = tid + 256*j; int row = f >> 3, c4 = f & 7;
        cp_async16(smem_u32(Bsm + row*APITCH + c4*4),
                   Wsrc + (size_t)(bn + row)*512 + kk + c4*4);
    }
}

template<int EPI>
__global__ void __launch_bounds__(256)
gemm_mma(GemmPair P)
{
    const int z = blockIdx.z;
    const float* A1 = P.A1[z]; const float* W1 = P.W1[z];
    const float* A2 = P.A2[z]; const float* W2 = P.W2[z];
    const float* bias = P.bias[z];
    float* out = P.out[z];
    const int nK = P.nK;

    extern __shared__ float sm[];
    const int bm = blockIdx.y * 128, bn = blockIdx.x * 128;
    const int tid = threadIdx.x, wid = tid >> 5, lane = tid & 31;
    const int wm = (wid >> 1) * 32, wn = (wid & 1) * 64;

    float acc[2][8][4];
    #pragma unroll
    for (int i = 0; i < 2; i++)
        #pragma unroll
        for (int j = 0; j < 8; j++)
            #pragma unroll
            for (int q = 0; q < 4; q++) acc[i][j][q] = 0.f;

    const int nc = nK / KCH;

    // prologue: chunk 0 -> stage 0
    load_chunk(sm, A1, W1, bm, bn, 0, tid);
    asm volatile("cp.async.commit_group;");

    for (int kc = 0; kc < nc; kc++) {
        int s = kc & 1;
        if (kc + 1 < nc) {
            int k = (kc + 1) * KCH;
            const float* As = (k < 512) ? A1 : A2;
            const float* Ws = (k < 512) ? W1 : W2;
            load_chunk(sm + (s^1)*2*STG_FLTS, As, Ws, bm, bn, k & 511, tid);
            asm volatile("cp.async.commit_group;");
            asm volatile("cp.async.wait_group 1;");
        } else {
            asm volatile("cp.async.wait_group 0;");
        }
        __syncthreads();

        const float* Abase = sm + s*2*STG_FLTS + wm*APITCH;
        const float* Bbase = sm + s*2*STG_FLTS + STG_FLTS + wn*APITCH;
        #pragma unroll
        for (int k8 = 0; k8 < 4; k8++) {
            int kb = k8*8 + (lane & 3);
            uint32_t a[2][4];
            #pragma unroll
            for (int mi = 0; mi < 2; mi++) {
                const float* ap = Abase + (mi*16 + (lane >> 2))*APITCH + kb;
                a[mi][0] = __float_as_uint(ap[0]);
                a[mi][1] = __float_as_uint(ap[8*APITCH]);
                a[mi][2] = __float_as_uint(ap[4]);
                a[mi][3] = __float_as_uint(ap[8*APITCH + 4]);
            }
            #pragma unroll
            for (int ni = 0; ni < 8; ni++) {
                const float* bp = Bbase + (ni*8 + (lane >> 2))*APITCH + kb;
                uint32_t b0 = __float_as_uint(bp[0]);
                uint32_t b1 = __float_as_uint(bp[4]);
                mma_tf32(acc[0][ni], a[0], b0, b1);
                mma_tf32(acc[1][ni], a[1], b0, b1);
            }
        }
        __syncthreads();
    }

    // epilogue
    const int r0 = bm + wm + (lane >> 2);
    const int cbase = bn + wn + (lane & 3)*2;
    float bb0[8], bb1[8];
    #pragma unroll
    for (int ni = 0; ni < 8; ni++) {
        bb0[ni] = bias[cbase + ni*8];
        bb1[ni] = bias[cbase + ni*8 + 1];
    }
    #pragma unroll
    for (int mi = 0; mi < 2; mi++) {
        int row0 = r0 + mi*16, row1 = row0 + 8;
        #pragma unroll
        for (int ni = 0; ni < 8; ni++) {
            int col = cbase + ni*8;
            float v0 = acc[mi][ni][0] + bb0[ni];
            float v1 = acc[mi][ni][1] + bb1[ni];
            float v2 = acc[mi][ni][2] + bb0[ni];
            float v3 = acc[mi][ni][3] + bb1[ni];
            if (EPI == 1) {
                v0 = fmaxf(v0, 0.f); v1 = fmaxf(v1, 0.f);
                v2 = fmaxf(v2, 0.f); v3 = fmaxf(v3, 0.f);
            } else {
                float2 ea0 = *(const float2*)(P.e1 + (size_t)row0*512 + col);
                float2 eb0 = *(const float2*)(P.e2 + (size_t)row0*512 + col);
                float2 ea1 = *(const float2*)(P.e1 + (size_t)row1*512 + col);
                float2 eb1 = *(const float2*)(P.e2 + (size_t)row1*512 + col);
                float g0 = 1.f / (1.f + expf(-v0));
                float g1 = 1.f / (1.f + expf(-v1));
                float g2 = 1.f / (1.f + expf(-v2));
                float g3 = 1.f / (1.f + expf(-v3));
                v0 = g0*ea0.x + (1.f - g0)*eb0.x;
                v1 = g1*ea0.y + (1.f - g1)*eb0.y;
                v2 = g2*ea1.x + (1.f - g2)*eb1.x;
                v3 = g3*ea1.y + (1.f - g3)*eb1.y;
            }
            *(float2*)(out + (size_t)row0*512 + col) = make_float2(v0, v1);
            *(float2*)(out + (size_t)row1*512 + col) = make_float2(v2, v3);
        }
    }
}

// ---------------- output assembly ----------------
__global__ void copy_f4(const float4* __restrict__ src, float4* __restrict__ dst, int n4) {
    int i = blockIdx.x*blockDim.x + threadIdx.x;
    int stride = gridDim.x*blockDim.x;
    for (; i < n4; i += stride) dst[i] = src[i];
}

__global__ void add_f4(const float4* __restrict__ a, const float4* __restrict__ b,
                       float4* __restrict__ dst, int n4) {
    int i = blockIdx.x*blockDim.x + threadIdx.x;
    int stride = gridDim.x*blockDim.x;
    for (; i < n4; i += stride) {
        float4 x = a[i], y = b[i];
        dst[i] = make_float4(x.x+y.x, x.y+y.y, x.z+y.z, x.w+y.w);
    }
}

// gnn[s,b,:] = enc[s,b,:] + scattered node; po[b,:] = max_s gnn[s,b,:]
__global__ void fused_assemble(const float* __restrict__ enc, const float* __restrict__ node,
                               const int* __restrict__ invmap,
                               float* __restrict__ gnn, float* __restrict__ po) {
    int b = blockIdx.x;
    int d = blockIdx.y * 128 + threadIdx.x;
    size_t base = (size_t)b*DD + d;
    float m = -3.402823466e38f;
    for (int s = 0; s < SS; s++) {
        float v = enc[(size_t)s*BB*DD + base];
        int inv = __ldg(&invmap[b*SS + s]);
        if (inv >= 0) v += node[(size_t)inv*DD + d];
        gnn[(size_t)s*BB*DD + base] = v;
        m = fmaxf(m, v);
    }
    po[base] = m;
}

// ---------------- host launch ----------------
extern "C" void kernel_launch(void* const* d_in, const int* in_sizes, int n_in,
                              void* d_out, int out_size) {
    const float* enc    = (const float*)d_in[0];   // [S,B,D]
    const float* numenc = (const float*)d_in[1];   // [B,N,D]
    const int*   pos    = (const int*)d_in[2];     // [B,N]
    const int*   order  = (const int*)d_in[3];     // [B,N]
    const float* w_n1a  = (const float*)d_in[4];
    const float* b_n1a  = (const float*)d_in[5];
    const float* w_n1b  = (const float*)d_in[6];
    const float* b_n1b  = (const float*)d_in[7];
    const float* w_n2a  = (const float*)d_in[8];
    const float* b_n2a  = (const float*)d_in[9];
    const float* w_n2b  = (const float*)d_in[10];
    const float* b_n2b  = (const float*)d_in[11];
    const float* w_g    = (const float*)d_in[12];  // [H,4D,D]
    const float* b_g    = (const float*)d_in[13];
    const float* w_o    = (const float*)d_in[14];  // [H,2D,D]
    const float* b_o    = (const float*)d_in[15];

    float* out     = (float*)d_out;
    float* out_gnn = out;                                    // [S,B,D]
    float* out_ne  = out + (size_t)SS*BB*DD;                 // [B,N,D]
    float* out_po  = out_ne + (size_t)BB*NN*DD;              // [B,D]

    float *g_gt, *g_lt, *nodeA, *nodeB, *t1, *t2, *t3, *t4, *ni1, *ni2, *ninfo, *WT;
    int* invmap;
    cudaGetSymbolAddress((void**)&g_gt,   g_gt_buf);
    cudaGetSymbolAddress((void**)&g_lt,   g_lt_buf);
    cudaGetSymbolAddress((void**)&invmap, invmap_buf);
    cudaGetSymbolAddress((void**)&nodeA,  buf_nodeA);
    cudaGetSymbolAddress((void**)&nodeB,  buf_nodeB);
    cudaGetSymbolAddress((void**)&t1,     buf_t1);
    cudaGetSymbolAddress((void**)&t2,     buf_t2);
    cudaGetSymbolAddress((void**)&t3,     buf_t3);
    cudaGetSymbolAddress((void**)&t4,     buf_t4);
    cudaGetSymbolAddress((void**)&ni1,    buf_ni1);
    cudaGetSymbolAddress((void**)&ni2,    buf_ni2);
    cudaGetSymbolAddress((void**)&ninfo,  buf_ninfo);
    cudaGetSymbolAddress((void**)&WT,     buf_WT);

    cudaFuncSetAttribute(gemm_mma<1>, cudaFuncAttributeMaxDynamicSharedMemorySize, SMEM_DYN);
    cudaFuncSetAttribute(gemm_mma<2>, cudaFuncAttributeMaxDynamicSharedMemorySize, SMEM_DYN);

    dim3 tblk(16, 16), tthr(32, 8);

    build_graphs<<<BB, NN*NN>>>(order, g_gt, g_lt);
    build_invmap<<<BB, SS>>>(pos, invmap);
    copy_f4<<<2048, 256>>>((const float4*)numenc, (float4*)nodeA, MM*DD/4);

    // transpose all weights upfront (tf32-rounded, [N,K])
    for (int h = 0; h < HH; h++) {
        float* base = WT + (size_t)h*8*DD*DD;
        transpose_w<<<tblk, tthr>>>(w_n1a + (size_t)h*DD*DD, base + 0*(size_t)DD*DD);
        transpose_w<<<tblk, tthr>>>(w_n1b + (size_t)h*DD*DD, base + 1*(size_t)DD*DD);
        transpose_w<<<tblk, tthr>>>(w_n2a + (size_t)h*DD*DD, base + 2*(size_t)DD*DD);
        transpose_w<<<tblk, tthr>>>(w_n2b + (size_t)h*DD*DD, base + 3*(size_t)DD*DD);
        transpose_gate<<<tblk, tthr>>>(w_g + (size_t)h*4*DD*DD,
                                       base + 4*(size_t)DD*DD, base + 5*(size_t)DD*DD);
        transpose_w<<<tblk, tthr>>>(w_o + (size_t)h*2*DD*DD, base + 6*(size_t)DD*DD);
        transpose_w<<<tblk, tthr>>>(w_o + (size_t)h*2*DD*DD + (size_t)DD*DD,
                                    base + 7*(size_t)DD*DD);
    }

    float* node  = nodeA;
    float* nodeN = nodeB;
    for (int h = 0; h < HH; h++) {
        float* base = WT + (size_t)h*8*DD*DD;

        // agg both chains: u1 = g_gt @ node, u2 = g_lt @ node
        graph_agg2<<<dim3(BB,4,2), 128>>>(g_gt, g_lt, node, node, t1, t2);

        // stage a: v1 = relu(u1@w1a + b), v2 = relu(u2@w2a + b)
        {
            GemmPair P = {};
            P.A1[0]=t1; P.W1[0]=base+0*(size_t)DD*DD; P.bias[0]=b_n1a+h*DD; P.out[0]=t3;
            P.A1[1]=t2; P.W1[1]=base+2*(size_t)DD*DD; P.bias[1]=b_n2a+h*DD; P.out[1]=t4;
            P.nK = 512;
            gemm_mma<1><<<dim3(4,32,2), 256, SMEM_DYN>>>(P);
        }

        // agg both chains: u1b = g_gt @ v1, u2b = g_lt @ v2
        graph_agg2<<<dim3(BB,4,2), 128>>>(g_gt, g_lt, t3, t4, t1, t2);

        // stage b: ni1 = relu(u1b@w1b + b), ni2 = relu(u2b@w2b + b)
        {
            GemmPair P = {};
            P.A1[0]=t1; P.W1[0]=base+1*(size_t)DD*DD; P.bias[0]=b_n1b+h*DD; P.out[0]=ni1;
            P.A1[1]=t2; P.W1[1]=base+3*(size_t)DD*DD; P.bias[1]=b_n2b+h*DD; P.out[1]=ni2;
            P.nK = 512;
            gemm_mma<1><<<dim3(4,32,2), 256, SMEM_DYN>>>(P);
        }

        // gate: ninfo = sig(ni1@Wg1 + ni2@Wg2 + b_g)*ni1 + (1-.)*ni2
        {
            GemmPair P = {};
            P.A1[0]=ni1; P.W1[0]=base+4*(size_t)DD*DD;
            P.A2[0]=ni2; P.W2[0]=base+5*(size_t)DD*DD;
            P.bias[0]=b_g+h*DD; P.out[0]=ninfo;
            P.e1=ni1; P.e2=ni2; P.nK = 1024;
            gemm_mma<2><<<dim3(4,32,1), 256, SMEM_DYN>>>(P);
        }

        // out: node = relu(node@woA + ninfo@woB + b_o)
        {
            GemmPair P = {};
            P.A1[0]=node;  P.W1[0]=base+6*(size_t)DD*DD;
            P.A2[0]=ninfo; P.W2[0]=base+7*(size_t)DD*DD;
            P.bias[0]=b_o+h*DD; P.out[0]=nodeN; P.nK = 1024;
            gemm_mma<1><<<dim3(4,32,1), 256, SMEM_DYN>>>(P);
        }
        float* tmp = node; node = nodeN; nodeN = tmp;
    }

    fused_assemble<<<dim3(BB,4), 128>>>(enc, node, invmap, out_gnn, out_po);
    add_f4<<<2048, 256>>>((const float4*)numenc, (const float4*)node,
                          (float4*)out_ne, BB*NN*DD/4);
}

// round 4
// speedup vs baseline: 3.1966x; 1.0855x over previous
#include <cuda_runtime.h>
#include <math.h>
#include <stdint.h>

#define BB 128
#define SS 512
#define NN 32
#define DD 512
#define HH 2
#define MM (BB*NN)   // 4096 rows

#define KCH 32                 // K elements per pipeline chunk
#define APITCH 36              // smem row pitch in floats (conflict-free frags)
#define STG_FLTS (128*APITCH)  // 4608 floats per matrix per stage
#define STG2 (2*STG_FLTS)      // floats per stage (A+B)
#define NSTG 4
#define SMEM_DYN (NSTG*STG2*4)  // 147456 bytes

// ---------------- scratch (device globals; no allocation) ----------------
__device__ float g_gt_buf[BB*NN*NN];
__device__ float g_lt_buf[BB*NN*NN];
__device__ int   invmap_buf[BB*SS];
__device__ float buf_nodeA[MM*DD];
__device__ float buf_nodeB[MM*DD];
__device__ float buf_t1[MM*DD];
__device__ float buf_t2[MM*DD];
__device__ float buf_t3[MM*DD];
__device__ float buf_t4[MM*DD];
__device__ float buf_ni1[MM*DD];
__device__ float buf_ni2[MM*DD];
__device__ float buf_ninfo[MM*DD];
__device__ float buf_WT[16*DD*DD];   // transposed (tf32-rounded) weights [N,K]

// ---------------- helpers ----------------
__device__ __forceinline__ uint32_t smem_u32(const void* p) {
    return (uint32_t)__cvta_generic_to_shared(p);
}
__device__ __forceinline__ float to_tf32(float x) {
    uint32_t r; asm("cvt.rna.tf32.f32 %0, %1;" : "=r"(r) : "f"(x));
    return __uint_as_float(r);
}
__device__ __forceinline__ void cp_async16(uint32_t dst, const void* src) {
    asm volatile("cp.async.cg.shared.global [%0], [%1], 16;" :: "r"(dst), "l"(src));
}
__device__ __forceinline__ void mma_tf32(float* c, const uint32_t* a,
                                         uint32_t b0, uint32_t b1) {
    asm volatile("mma.sync.aligned.m16n8k8.row.col.f32.tf32.tf32.f32 "
                 "{%0,%1,%2,%3}, {%4,%5,%6,%7}, {%8,%9}, {%0,%1,%2,%3};"
                 : "+f"(c[0]), "+f"(c[1]), "+f"(c[2]), "+f"(c[3])
                 : "r"(a[0]), "r"(a[1]), "r"(a[2]), "r"(a[3]), "r"(b0), "r"(b1));
}

// ---------------- graph construction (+ invmap) ----------------
__global__ void build_graphs_inv(const int* __restrict__ order, const int* __restrict__ pos,
                                 float* __restrict__ g_gt, float* __restrict__ g_lt,
                                 int* __restrict__ invmap) {
    int b = blockIdx.x;
    __shared__ int ord[NN];
    int tid = threadIdx.x;              // 1024 threads = NN*NN
    if (tid < NN) ord[tid] = order[b*NN + tid];
    if (tid < SS) invmap[b*SS + tid] = -1;
    if (tid >= 512 && tid < 1024) invmap[b*SS + tid - 512] = -1;  // covers full SS=512? no-op
    __syncthreads();
    if (tid < NN) {
        int p = pos[b*NN + tid];
        if (p >= 0) invmap[b*SS + p] = b*NN + tid;
    }
    int n = tid >> 5, m = tid & 31;
    int on = ord[n], om = ord[m];
    float pair = (on > 0 && om > 0 && n != m) ? 1.f : 0.f;
    float eye  = (n == m) ? 1.f : 0.f;
    float vg = pair * ((on > om) ? 1.f : 0.f) + eye;
    float vl = pair * ((on > om) ? 0.f : 1.f) + eye;
    float sg = vg, sl = vl;
    #pragma unroll
    for (int off = 16; off; off >>= 1) {
        sg += __shfl_xor_sync(0xffffffffu, sg, off);
        sl += __shfl_xor_sync(0xffffffffu, sl, off);
    }
    g_gt[b*NN*NN + tid] = vg / sg;
    g_lt[b*NN*NN + tid] = vl / sl;
}

// ---------------- dual graph aggregation (z=0: gt/x0->y0, z=1: lt/x1->y1) ------
__global__ void graph_agg2(const float* __restrict__ g_gt, const float* __restrict__ g_lt,
                           const float* __restrict__ x0, const float* __restrict__ x1,
                           float* __restrict__ y0, float* __restrict__ y1) {
    int b = blockIdx.x;
    const float* g = blockIdx.z ? g_lt : g_gt;
    const float* x = blockIdx.z ? x1 : x0;
    float* y       = blockIdx.z ? y1 : y0;
    int d = blockIdx.y * 128 + threadIdx.x;    // 128 threads
    __shared__ float gs[NN*NN];
    for (int i = threadIdx.x; i < NN*NN; i += 128) gs[i] = g[b*NN*NN + i];
    __syncthreads();
    const float* xb = x + (size_t)b*NN*DD + d;
    float xv[NN];
    #pragma unroll
    for (int m = 0; m < NN; m++) xv[m] = xb[(size_t)m*DD];
    float* yb = y + (size_t)b*NN*DD + d;
    #pragma unroll
    for (int n = 0; n < NN; n++) {
        float acc = 0.f;
        #pragma unroll
        for (int m = 0; m < NN; m++) acc = fmaf(gs[n*NN+m], xv[m], acc);
        yb[(size_t)n*DD] = acc;
    }
}

// ---------------- single-launch weight transpose ([K,N]->[N,K], tf32-rounded) ---
struct TJob { const float* src; float* d1; float* d2; int gate; };
struct TArgs { TJob j[14]; };

__global__ void transpose_all(TArgs A) {
    TJob job = A.j[blockIdx.z];
    __shared__ float t1s[32][33], t2s[32][33];
    int k0 = blockIdx.x*32, n0 = blockIdx.y*32;
    int tx = threadIdx.x, ty = threadIdx.y;
    if (!job.gate) {
        #pragma unroll
        for (int i = 0; i < 4; i++)
            t1s[ty + i*8][tx] = job.src[(size_t)(k0 + ty + i*8)*DD + n0 + tx];
        __syncthreads();
        #pragma unroll
        for (int i = 0; i < 4; i++)
            job.d1[(size_t)(n0 + ty + i*8)*DD + k0 + tx] = to_tf32(t1s[tx][ty + i*8]);
    } else {
        #pragma unroll
        for (int i = 0; i < 4; i++) {
            int k = k0 + ty + i*8, n = n0 + tx;
            float w0 = job.src[(size_t)k*DD + n];
            float w1 = job.src[(size_t)(DD + k)*DD + n];
            float w2 = job.src[(size_t)(2*DD + k)*DD + n];
            float w3 = job.src[(size_t)(3*DD + k)*DD + n];
            t1s[ty + i*8][tx] = w0 + w2 + w3;
            t2s[ty + i*8][tx] = w1 + w2 - w3;
        }
        __syncthreads();
        #pragma unroll
        for (int i = 0; i < 4; i++) {
            size_t o = (size_t)(n0 + ty + i*8)*DD + k0 + tx;
            job.d1[o] = to_tf32(t1s[tx][ty + i*8]);
            job.d2[o] = to_tf32(t2s[tx][ty + i*8]);
        }
    }
}

// ---------------- TF32 mma.sync GEMM ----------------
struct GemmPair {
    const float *A1[2], *W1[2], *A2[2], *W2[2], *bias[2];
    const float *e1, *e2;
    float *out[2];
    int nK;
};

__device__ __forceinline__ void load_chunk(float* smbase, const float* Asrc,
                                           const float* Wsrc, int bm, int bn,
                                           int kk, int tid) {
    float* Asm = smbase;
    float* Bsm = smbase + STG_FLTS;
    #pragma unroll
    for (int j = 0; j < 4; j++) {
        int f = tid + 256*j; int row = f >> 3, c4 = f & 7;
        cp_async16(smem_u32(Asm + row*APITCH + c4*4),
                   Asrc + (size_t)(bm + row)*512 + kk + c4*4);
    }
    #pragma unroll
    for (int j = 0; j < 4; j++) {
        int f = tid + 256*j; int row = f >> 3, c4 = f & 7;
        cp_async16(smem_u32(Bsm + row*APITCH + c4*4),
                   Wsrc + (size_t)(bn + row)*512 + kk + c4*4);
    }
}

#define FRAG_LOAD(buf, k8) do {                                              \
    int kb_ = (k8)*8 + (lane & 3);                                           \
    _Pragma("unroll")                                                        \
    for (int mi_ = 0; mi_ < 2; mi_++) {                                      \
        const float* ap_ = Abase + (mi_*16 + (lane >> 2))*APITCH + kb_;      \
        aR[buf][mi_][0] = __float_as_uint(ap_[0]);                           \
        aR[buf][mi_][1] = __float_as_uint(ap_[8*APITCH]);                    \
        aR[buf][mi_][2] = __float_as_uint(ap_[4]);                           \
        aR[buf][mi_][3] = __float_as_uint(ap_[8*APITCH + 4]);                \
    }                                                                        \
    _Pragma("unroll")                                                        \
    for (int ni_ = 0; ni_ < 8; ni_++) {                                      \
        const float* bp_ = Bbase + (ni_*8 + (lane >> 2))*APITCH + kb_;       \
        bR[buf][ni_][0] = __float_as_uint(bp_[0]);                           \
        bR[buf][ni_][1] = __float_as_uint(bp_[4]);                           \
    }                                                                        \
} while (0)

template<int EPI>
__global__ void __launch_bounds__(256)
gemm_mma(GemmPair P)
{
    const int z = blockIdx.z;
    const float* A1 = P.A1[z]; const float* W1 = P.W1[z];
    const float* A2 = P.A2[z]; const float* W2 = P.W2[z];
    const float* bias = P.bias[z];
    float* out = P.out[z];
    const int nK = P.nK;

    extern __shared__ float sm[];
    const int bm = blockIdx.y * 128, bn = blockIdx.x * 128;
    const int tid = threadIdx.x, wid = tid >> 5, lane = tid & 31;
    const int wm = (wid >> 1) * 32, wn = (wid & 1) * 64;

    float acc[2][8][4];
    #pragma unroll
    for (int i = 0; i < 2; i++)
        #pragma unroll
        for (int j = 0; j < 8; j++)
            #pragma unroll
            for (int q = 0; q < 4; q++) acc[i][j][q] = 0.f;

    const int nc = nK / KCH;

    // prologue: chunks 0,1
    load_chunk(sm, A1, W1, bm, bn, 0, tid);
    asm volatile("cp.async.commit_group;");
    {
        const float* As = (KCH < 512) ? A1 : A2;
        const float* Ws = (KCH < 512) ? W1 : W2;
        load_chunk(sm + STG2, As, Ws, bm, bn, KCH & 511, tid);
        asm volatile("cp.async.commit_group;");
    }

    for (int kc = 0; kc < nc; kc++) {
        int s = kc & 3;
        if (kc + 2 < nc) {
            int k = (kc + 2) * KCH;
            const float* As = (k < 512) ? A1 : A2;
            const float* Ws = (k < 512) ? W1 : W2;
            load_chunk(sm + ((kc + 2) & 3)*STG2, As, Ws, bm, bn, k & 511, tid);
            asm volatile("cp.async.commit_group;");
            asm volatile("cp.async.wait_group 2;");
        } else if (kc + 1 < nc) {
            asm volatile("cp.async.wait_group 1;");
        } else {
            asm volatile("cp.async.wait_group 0;");
        }
        __syncthreads();

        const float* Abase = sm + s*STG2 + wm*APITCH;
        const float* Bbase = sm + s*STG2 + STG_FLTS + wn*APITCH;

        uint32_t aR[2][2][4];
        uint32_t bR[2][8][2];
        FRAG_LOAD(0, 0);
        #pragma unroll
        for (int k8 = 0; k8 < 4; k8++) {
            int cur = k8 & 1;
            if (k8 < 3) {
                int nxt = (k8 + 1) & 1;
                FRAG_LOAD(nxt, k8 + 1);
            }
            #pragma unroll
            for (int ni = 0; ni < 8; ni++) {
                mma_tf32(acc[0][ni], aR[cur][0], bR[cur][ni][0], bR[cur][ni][1]);
                mma_tf32(acc[1][ni], aR[cur][1], bR[cur][ni][0], bR[cur][ni][1]);
            }
        }
    }

    // epilogue
    const int r0 = bm + wm + (lane >> 2);
    const int cbase = bn + wn + (lane & 3)*2;
    float bb0[8], bb1[8];
    #pragma unroll
    for (int ni = 0; ni < 8; ni++) {
        bb0[ni] = bias[cbase + ni*8];
        bb1[ni] = bias[cbase + ni*8 + 1];
    }
    #pragma unroll
    for (int mi = 0; mi < 2; mi++) {
        int row0 = r0 + mi*16, row1 = row0 + 8;
        #pragma unroll
        for (int ni = 0; ni < 8; ni++) {
            int col = cbase + ni*8;
            float v0 = acc[mi][ni][0] + bb0[ni];
            float v1 = acc[mi][ni][1] + bb1[ni];
            float v2 = acc[mi][ni][2] + bb0[ni];
            float v3 = acc[mi][ni][3] + bb1[ni];
            if (EPI == 1) {
                v0 = fmaxf(v0, 0.f); v1 = fmaxf(v1, 0.f);
                v2 = fmaxf(v2, 0.f); v3 = fmaxf(v3, 0.f);
            } else {
                float2 ea0 = *(const float2*)(P.e1 + (size_t)row0*512 + col);
                float2 eb0 = *(const float2*)(P.e2 + (size_t)row0*512 + col);
                float2 ea1 = *(const float2*)(P.e1 + (size_t)row1*512 + col);
                float2 eb1 = *(const float2*)(P.e2 + (size_t)row1*512 + col);
                float g0 = 1.f / (1.f + expf(-v0));
                float g1 = 1.f / (1.f + expf(-v1));
                float g2 = 1.f / (1.f + expf(-v2));
                float g3 = 1.f / (1.f + expf(-v3));
                v0 = g0*ea0.x + (1.f - g0)*eb0.x;
                v1 = g1*ea0.y + (1.f - g1)*eb0.y;
                v2 = g2*ea1.x + (1.f - g2)*eb1.x;
                v3 = g3*ea1.y + (1.f - g3)*eb1.y;
            }
            *(float2*)(out + (size_t)row0*512 + col) = make_float2(v0, v1);
            *(float2*)(out + (size_t)row1*512 + col) = make_float2(v2, v3);
        }
    }
}

// ---------------- output assembly ----------------
__global__ void add_f4(const float4* __restrict__ a, const float4* __restrict__ b,
                       float4* __restrict__ dst, int n4) {
    int i = blockIdx.x*blockDim.x + threadIdx.x;
    int stride = gridDim.x*blockDim.x;
    for (; i < n4; i += stride) {
        float4 x = a[i], y = b[i];
        dst[i] = make_float4(x.x+y.x, x.y+y.y, x.z+y.z, x.w+y.w);
    }
}

// gnn[s,b,:] = enc[s,b,:] + scattered node; po[b,:] = max_s gnn[s,b,:]
__global__ void fused_assemble(const float* __restrict__ enc, const float* __restrict__ node,
                               const int* __restrict__ invmap,
                               float* __restrict__ gnn, float* __restrict__ po) {
    int b = blockIdx.x;
    int d = blockIdx.y * 128 + threadIdx.x;
    __shared__ int inv[SS];
    for (int i = threadIdx.x; i < SS; i += 128) inv[i] = invmap[b*SS + i];
    __syncthreads();
    size_t base = (size_t)b*DD + d;
    float m = -3.402823466e38f;
    #pragma unroll 1
    for (int s = 0; s < SS; s += 4) {
        float v[4];
        #pragma unroll
        for (int u = 0; u < 4; u++)
            v[u] = enc[(size_t)(s + u)*BB*DD + base];
        #pragma unroll
        for (int u = 0; u < 4; u++) {
            int iv = inv[s + u];
            if (iv >= 0) v[u] += node[(size_t)iv*DD + d];
        }
        #pragma unroll
        for (int u = 0; u < 4; u++) {
            gnn[(size_t)(s + u)*BB*DD + base] = v[u];
            m = fmaxf(m, v[u]);
        }
    }
    po[base] = m;
}

// ---------------- host launch ----------------
extern "C" void kernel_launch(void* const* d_in, const int* in_sizes, int n_in,
                              void* d_out, int out_size) {
    const float* enc    = (const float*)d_in[0];   // [S,B,D]
    const float* numenc = (const float*)d_in[1];   // [B,N,D]
    const int*   pos    = (const int*)d_in[2];     // [B,N]
    const int*   order  = (const int*)d_in[3];     // [B,N]
    const float* w_n1a  = (const float*)d_in[4];
    const float* b_n1a  = (const float*)d_in[5];
    const float* w_n1b  = (const float*)d_in[6];
    const float* b_n1b  = (const float*)d_in[7];
    const float* w_n2a  = (const float*)d_in[8];
    const float* b_n2a  = (const float*)d_in[9];
    const float* w_n2b  = (const float*)d_in[10];
    const float* b_n2b  = (const float*)d_in[11];
    const float* w_g    = (const float*)d_in[12];  // [H,4D,D]
    const float* b_g    = (const float*)d_in[13];
    const float* w_o    = (const float*)d_in[14];  // [H,2D,D]
    const float* b_o    = (const float*)d_in[15];

    float* out     = (float*)d_out;
    float* out_gnn = out;                                    // [S,B,D]
    float* out_ne  = out + (size_t)SS*BB*DD;                 // [B,N,D]
    float* out_po  = out_ne + (size_t)BB*NN*DD;              // [B,D]

    float *g_gt, *g_lt, *nodeA, *nodeB, *t1, *t2, *t3, *t4, *ni1, *ni2, *ninfo, *WT;
    int* invmap;
    cudaGetSymbolAddress((void**)&g_gt,   g_gt_buf);
    cudaGetSymbolAddress((void**)&g_lt,   g_lt_buf);
    cudaGetSymbolAddress((void**)&invmap, invmap_buf);
    cudaGetSymbolAddress((void**)&nodeA,  buf_nodeA);
    cudaGetSymbolAddress((void**)&nodeB,  buf_nodeB);
    cudaGetSymbolAddress((void**)&t1,     buf_t1);
    cudaGetSymbolAddress((void**)&t2,     buf_t2);
    cudaGetSymbolAddress((void**)&t3,     buf_t3);
    cudaGetSymbolAddress((void**)&t4,     buf_t4);
    cudaGetSymbolAddress((void**)&ni1,    buf_ni1);
    cudaGetSymbolAddress((void**)&ni2,    buf_ni2);
    cudaGetSymbolAddress((void**)&ninfo,  buf_ninfo);
    cudaGetSymbolAddress((void**)&WT,     buf_WT);

    cudaFuncSetAttribute(gemm_mma<1>, cudaFuncAttributeMaxDynamicSharedMemorySize, SMEM_DYN);
    cudaFuncSetAttribute(gemm_mma<2>, cudaFuncAttributeMaxDynamicSharedMemorySize, SMEM_DYN);

    build_graphs_inv<<<BB, NN*NN>>>(order, pos, g_gt, g_lt, invmap);

    // all weight transposes in one launch
    {
        TArgs TA;
        for (int h = 0; h < HH; h++) {
            float* base = WT + (size_t)h*8*DD*DD;
            TJob* j = TA.j + h*7;
            j[0] = { w_n1a + (size_t)h*DD*DD, base + 0*(size_t)DD*DD, nullptr, 0 };
            j[1] = { w_n1b + (size_t)h*DD*DD, base + 1*(size_t)DD*DD, nullptr, 0 };
            j[2] = { w_n2a + (size_t)h*DD*DD, base + 2*(size_t)DD*DD, nullptr, 0 };
            j[3] = { w_n2b + (size_t)h*DD*DD, base + 3*(size_t)DD*DD, nullptr, 0 };
            j[4] = { w_o + (size_t)h*2*DD*DD,                  base + 6*(size_t)DD*DD, nullptr, 0 };
            j[5] = { w_o + (size_t)h*2*DD*DD + (size_t)DD*DD,  base + 7*(size_t)DD*DD, nullptr, 0 };
            j[6] = { w_g + (size_t)h*4*DD*DD, base + 4*(size_t)DD*DD, base + 5*(size_t)DD*DD, 1 };
        }
        transpose_all<<<dim3(16,16,14), dim3(32,8)>>>(TA);
    }

    const float* node = numenc;          // hop-0 input read directly
    float* nodeOut[2] = { nodeA, nodeB };
    for (int h = 0; h < HH; h++) {
        float* base = WT + (size_t)h*8*DD*DD;

        // u1 = g_gt @ node, u2 = g_lt @ node
        graph_agg2<<<dim3(BB,4,2), 128>>>(g_gt, g_lt, node, node, t1, t2);

        // v1 = relu(u1@w1a + b), v2 = relu(u2@w2a + b)
        {
            GemmPair P = {};
            P.A1[0]=t1; P.W1[0]=base+0*(size_t)DD*DD; P.bias[0]=b_n1a+h*DD; P.out[0]=t3;
            P.A1[1]=t2; P.W1[1]=base+2*(size_t)DD*DD; P.bias[1]=b_n2a+h*DD; P.out[1]=t4;
            P.nK = 512;
            gemm_mma<1><<<dim3(4,32,2), 256, SMEM_DYN>>>(P);
        }

        // u1b = g_gt @ v1, u2b = g_lt @ v2
        graph_agg2<<<dim3(BB,4,2), 128>>>(g_gt, g_lt, t3, t4, t1, t2);

        // ni1 = relu(u1b@w1b + b), ni2 = relu(u2b@w2b + b)
        {
            GemmPair P = {};
            P.A1[0]=t1; P.W1[0]=base+1*(size_t)DD*DD; P.bias[0]=b_n1b+h*DD; P.out[0]=ni1;
            P.A1[1]=t2; P.W1[1]=base+3*(size_t)DD*DD; P.bias[1]=b_n2b+h*DD; P.out[1]=ni2;
            P.nK = 512;
            gemm_mma<1><<<dim3(4,32,2), 256, SMEM_DYN>>>(P);
        }

        // ninfo = sig(ni1@Wg1 + ni2@Wg2 + b_g)*ni1 + (1-.)*ni2
        {
            GemmPair P = {};
            P.A1[0]=ni1; P.W1[0]=base+4*(size_t)DD*DD;
            P.A2[0]=ni2; P.W2[0]=base+5*(size_t)DD*DD;
            P.bias[0]=b_g+h*DD; P.out[0]=ninfo;
            P.e1=ni1; P.e2=ni2; P.nK = 1024;
            gemm_mma<2><<<dim3(4,32,1), 256, SMEM_DYN>>>(P);
        }

        // node' = relu(node@woA + ninfo@woB + b_o)
        {
            GemmPair P = {};
            P.A1[0]=node;  P.W1[0]=base+6*(size_t)DD*DD;
            P.A2[0]=ninfo; P.W2[0]=base+7*(size_t)DD*DD;
            P.bias[0]=b_o+h*DD; P.out[0]=nodeOut[h]; P.nK = 1024;
            gemm_mma<1><<<dim3(4,32,1), 256, SMEM_DYN>>>(P);
        }
        node = nodeOut[h];
    }

    fused_assemble<<<dim3(BB,4), 128>>>(enc, node, invmap, out_gnn, out_po);
    add_f4<<<2048, 256>>>((const float4*)numenc, (const float4*)node,
                          (float4*)out_ne, MM*DD/4);
}